// round 15
// baseline (speedup 1.0000x reference)
#include <cuda_runtime.h>

#define WSZ   7
#define W     15
#define WW    225
#define NC    8
#define CWW   1800                   // floats per (b,p) output row
#define LSEQ  4096
#define PLEN  (LSEQ - 2*WSZ)         // 4082
#define NB    16

#define PP       16                  // p-values per block
#define NPCHUNK  ((PLEN + PP - 1) / PP)   // 256
#define NT       480
#define NQUAD    450                 // 1800/4 quads per row
#define NWIN     (PP + 2*WSZ)        // 30 staged window columns
#define TROW     32
#define BROW     36

__global__ __launch_bounds__(NT, 4)
void local_interactions_kernel(const float* __restrict__ in, float* __restrict__ out)
{
    // Phase-replicated copies: s4x[c][ph][m] = orig[c][m+ph-4];
    // orig[x..x+3] = aligned float4 at ph=(x+4)&3, m0=(x+4)&~3.
    __shared__ float stopp[NC][TROW];
    __shared__ float s4t[NC][4][BROW];
    __shared__ float s4b[NC][4][BROW];

    const int tid = threadIdx.x;
    const int pc  = blockIdx.x;
    const int b   = blockIdx.y;
    const int p0  = min(pc * PP, PLEN - PP);   // overlap-clamp tail (deterministic)

    const float2* in2 = reinterpret_cast<const float2*>(in);
    for (int t = tid; t < NC * NWIN; t += NT) {
        const int c = t / NWIN;
        const int q = t - c * NWIN;
        float2 v = in2[(size_t)(b * NC + c) * LSEQ + (p0 + q)];
        stopp[c][q] = v.x;
        #pragma unroll
        for (int ph = 0; ph < 4; ++ph) {
            s4t[c][ph][q + 4 - ph] = v.x;
            s4b[c][ph][q + 4 - ph] = v.y;
        }
    }
    __syncthreads();

    if (tid >= NQUAD) return;

    // ---- Decode quad: slot0 (cA,iA,jA); row-cross at slot k when jA>11 ----
    const int e0   = tid << 2;
    const int cA   = e0 / WW;
    const int remA = e0 - cA * WW;
    const int iA   = remA / W;
    const int jA   = remA - iA * W;
    const int k    = (jA <= W - 4) ? 4 : (W - jA);  // 4 = no cross
    const bool cross = (k < 4);

    int cB = cA, iB = iA;
    if (cross) {
        const int ek = e0 + k;
        cB = ek / WW;
        iB = (ek - cB * WW) / W;                    // jB == 0
    }

    const float* s4b_f = &s4b[0][0][0];
    const float* s4t_f = &s4t[0][0][0];

    const unsigned ja4 = (unsigned)(jA + 4), ia4 = (unsigned)(iA + 4);
    const unsigned offBA = (unsigned)(cA * 4 + (ja4 & 3u)) * BROW + (ja4 & ~3u);
    const unsigned offTA = (unsigned)(cA * 4 + (ia4 & 3u)) * BROW + (ia4 & ~3u);

    unsigned offB[4];
    #pragma unroll
    for (int u = 0; u < 4; ++u) {
        const unsigned xb4 = (unsigned)(u - k + 4);          // in [1,7]
        offB[u] = (unsigned)(cB * 4 + (xb4 & 3u)) * BROW + (xb4 & ~3u);
    }
    const float* topB = &stopp[cB][iB];

    float* ob = out + (size_t)(b * PLEN + p0) * CWW + e0;

    float4 bcur = *reinterpret_cast<const float4*>(s4b_f + offBA);

    #pragma unroll
    for (int n = 0; n < PP / 4; ++n) {
        const float4 bnxt = *reinterpret_cast<const float4*>(s4b_f + offBA + 4 * (n + 1));
        const float4 tq   = *reinterpret_cast<const float4*>(s4t_f + offTA + 4 * n);
        const float  ta[4] = { tq.x, tq.y, tq.z, tq.w };
        const float  bw[8] = { bcur.x, bcur.y, bcur.z, bcur.w,
                               bnxt.x, bnxt.y, bnxt.z, bnxt.w };
        #pragma unroll
        for (int u = 0; u < 4; ++u) {
            const int lp = 4 * n + u;
            float  Tb = 0.0f;
            float4 Bb = make_float4(0.f, 0.f, 0.f, 0.f);
            if (cross) {                            // predicated (~20% of lanes)
                Tb = topB[lp];
                Bb = *reinterpret_cast<const float4*>(s4b_f + offB[u] + 4 * n);
            }
            float4 v;
            v.x = (0 >= k) ? Tb * Bb.x : ta[u] * bw[u + 0];
            v.y = (1 >= k) ? Tb * Bb.y : ta[u] * bw[u + 1];
            v.z = (2 >= k) ? Tb * Bb.z : ta[u] * bw[u + 2];
            v.w = (3 >= k) ? Tb * Bb.w : ta[u] * bw[u + 3];
            *reinterpret_cast<float4*>(ob + (size_t)lp * CWW) = v;  // default policy
        }
        bcur = bnxt;
    }
}

extern "C" void kernel_launch(void* const* d_in, const int* in_sizes, int n_in,
                              void* d_out, int out_size)
{
    const float* in  = (const float*)d_in[0];
    float*       out = (float*)d_out;
    dim3 grid(NPCHUNK, NB);
    local_interactions_kernel<<<grid, NT>>>(in, out);
}

// round 16
// speedup vs baseline: 1.0625x; 1.0625x over previous
#include <cuda_runtime.h>

#define WSZ   7
#define W     15
#define WW    225
#define NC    8
#define CWW   1800                   // floats per (b,p) output row
#define LSEQ  4096
#define PLEN  (LSEQ - 2*WSZ)         // 4082
#define NB    16

#define PP       16                  // p-values per block
#define NPCHUNK  ((PLEN + PP - 1) / PP)   // 256
#define NT       480
#define NQUAD    450                 // 1800/4 quads per row
#define NWIN     (PP + 2*WSZ)        // 30 staged window columns
#define TROW     32
#define BROW     36

__global__ __launch_bounds__(NT, 4)
void local_interactions_kernel(const float* __restrict__ in, float* __restrict__ out)
{
    // Phase-replicated copies: s4x[c][ph][m] = orig[c][m+ph-4];
    // orig[x..x+3] = aligned float4 at ph=(x+4)&3, m0=(x+4)&~3.
    __shared__ float stopp[NC][TROW];
    __shared__ float s4t[NC][4][BROW];
    __shared__ float s4b[NC][4][BROW];

    const int tid = threadIdx.x;
    const int pc  = blockIdx.x;
    const int b   = blockIdx.y;
    const int p0  = min(pc * PP, PLEN - PP);   // overlap-clamp tail (deterministic)

    const float2* in2 = reinterpret_cast<const float2*>(in);
    for (int t = tid; t < NC * NWIN; t += NT) {
        const int c = t / NWIN;
        const int q = t - c * NWIN;
        float2 v = in2[(size_t)(b * NC + c) * LSEQ + (p0 + q)];
        stopp[c][q] = v.x;
        #pragma unroll
        for (int ph = 0; ph < 4; ++ph) {
            s4t[c][ph][q + 4 - ph] = v.x;
            s4b[c][ph][q + 4 - ph] = v.y;
        }
    }
    __syncthreads();

    if (tid >= NQUAD) return;

    // ---- Decode quad: slot0 (cA,iA,jA); row-cross at slot k when jA>11 ----
    const int e0   = tid << 2;
    const int cA   = e0 / WW;
    const int remA = e0 - cA * WW;
    const int iA   = remA / W;
    const int jA   = remA - iA * W;
    const int k    = (jA <= W - 4) ? 4 : (W - jA);  // 4 = no cross
    const bool cross = (k < 4);

    int cB = cA, iB = iA;
    if (cross) {
        const int ek = e0 + k;
        cB = ek / WW;
        iB = (ek - cB * WW) / W;                    // jB == 0
    }

    const float* s4b_f = &s4b[0][0][0];
    const float* s4t_f = &s4t[0][0][0];

    const unsigned ja4 = (unsigned)(jA + 4), ia4 = (unsigned)(iA + 4);
    const unsigned offBA = (unsigned)(cA * 4 + (ja4 & 3u)) * BROW + (ja4 & ~3u);
    const unsigned offTA = (unsigned)(cA * 4 + (ia4 & 3u)) * BROW + (ia4 & ~3u);

    unsigned offB[4];
    #pragma unroll
    for (int u = 0; u < 4; ++u) {
        const unsigned xb4 = (unsigned)(u - k + 4);          // in [1,7]
        offB[u] = (unsigned)(cB * 4 + (xb4 & 3u)) * BROW + (xb4 & ~3u);
    }
    const float* topB = &stopp[cB][iB];

    float* ob = out + (size_t)(b * PLEN + p0) * CWW + e0;

    float4 bcur = *reinterpret_cast<const float4*>(s4b_f + offBA);

    #pragma unroll
    for (int n = 0; n < PP / 4; ++n) {
        const float4 bnxt = *reinterpret_cast<const float4*>(s4b_f + offBA + 4 * (n + 1));
        const float4 tq   = *reinterpret_cast<const float4*>(s4t_f + offTA + 4 * n);
        const float  ta[4] = { tq.x, tq.y, tq.z, tq.w };
        const float  bw[8] = { bcur.x, bcur.y, bcur.z, bcur.w,
                               bnxt.x, bnxt.y, bnxt.z, bnxt.w };
        #pragma unroll
        for (int u = 0; u < 4; ++u) {
            const int lp = 4 * n + u;
            float  Tb = 0.0f;
            float4 Bb = make_float4(0.f, 0.f, 0.f, 0.f);
            if (cross) {                            // predicated (~20% of lanes)
                Tb = topB[lp];
                Bb = *reinterpret_cast<const float4*>(s4b_f + offB[u] + 4 * n);
            }
            float4 v;
            v.x = (0 >= k) ? Tb * Bb.x : ta[u] * bw[u + 0];
            v.y = (1 >= k) ? Tb * Bb.y : ta[u] * bw[u + 1];
            v.z = (2 >= k) ? Tb * Bb.z : ta[u] * bw[u + 2];
            v.w = (3 >= k) ? Tb * Bb.w : ta[u] * bw[u + 3];
            __stcs(reinterpret_cast<float4*>(ob + (size_t)lp * CWW), v);
        }
        bcur = bnxt;
    }
}

extern "C" void kernel_launch(void* const* d_in, const int* in_sizes, int n_in,
                              void* d_out, int out_size)
{
    const float* in  = (const float*)d_in[0];
    float*       out = (float*)d_out;
    dim3 grid(NPCHUNK, NB);
    local_interactions_kernel<<<grid, NT>>>(in, out);
}